// round 2
// baseline (speedup 1.0000x reference)
#include <cuda_runtime.h>
#include <math.h>

#define BATCH 64
#define SEQ   2048
#define DIN   256
#define DOUT  256
#define MTOT  (BATCH * SEQ)

// ---------------------------------------------------------------------------
// Bit-exact replica of XLA's EmitFastTanh (Eigen generic_fast_tanh_float,
// with-FMA variant): clamp to +/-7.99881172180175781, |x|<4e-4 -> x,
// rational P13/Q6 Horner in x^2 with fused FMA, IEEE division.
// ---------------------------------------------------------------------------
__device__ __forceinline__ float xla_tanh(float x)
{
    const float kPlusClamp  = 7.99881172180175781f;
    const float kMinusClamp = -7.99881172180175781f;
    const float kTiny       = 0.0004f;

    const float a1  = 4.89352455891786e-03f;
    const float a3  = 6.37261928875436e-04f;
    const float a5  = 1.48572235717979e-05f;
    const float a7  = 5.12229709037114e-08f;
    const float a9  = -8.60467152213735e-11f;
    const float a11 = 2.00018790482477e-13f;
    const float a13 = -2.76076847742355e-16f;
    const float b0  = 4.89352518554385e-03f;
    const float b2  = 2.26843463243900e-03f;
    const float b4  = 1.18534705686654e-04f;
    const float b6  = 1.19825839466702e-06f;

    float ax = fabsf(x);
    float xc = fminf(fmaxf(x, kMinusClamp), kPlusClamp);
    float x2 = __fmul_rn(xc, xc);

    float p = __fmaf_rn(x2, a13, a11);
    p = __fmaf_rn(x2, p, a9);
    p = __fmaf_rn(x2, p, a7);
    p = __fmaf_rn(x2, p, a5);
    p = __fmaf_rn(x2, p, a3);
    p = __fmaf_rn(x2, p, a1);
    p = __fmul_rn(xc, p);

    float q = __fmaf_rn(x2, b6, b4);
    q = __fmaf_rn(x2, q, b2);
    q = __fmaf_rn(x2, q, b0);

    float r = __fdiv_rn(p, q);
    return (ax < kTiny) ? x : r;
}

// ---------------------------------------------------------------------------
// Kernel 1: zx = input @ W_x + (b_x + b_h)  ->  written into y region of d_out.
// Every output element is a SINGLE fp32 accumulator over ascending k with
// fused FMA — bit-identical to Eigen/cuBLAS fp32 accumulation order.
// ---------------------------------------------------------------------------
__global__ __launch_bounds__(256, 2) void gemm_zx_kernel(
    const float* __restrict__ A,    // [MTOT][DIN]
    const float* __restrict__ W,    // [DIN][DOUT]
    const float* __restrict__ b_h,
    const float* __restrict__ b_x,
    float* __restrict__ C)          // [MTOT][DOUT]
{
    __shared__ float As[64 * 36];
    __shared__ float Bs[32 * 64];
    __shared__ float bias[64];

    const int tid = threadIdx.x;
    const int tx = tid & 15;
    const int ty = tid >> 4;
    const long m0 = (long)blockIdx.x * 64;
    const int n0 = blockIdx.y * 64;

    if (tid < 64) bias[tid] = __fadd_rn(b_h[n0 + tid], b_x[n0 + tid]);

    float acc[16];
#pragma unroll
    for (int i = 0; i < 16; ++i) acc[i] = 0.f;

    for (int kc = 0; kc < DIN; kc += 32) {
        __syncthreads();
        {
            int i0 = tid, i1 = tid + 256;
            int r0 = i0 >> 3, c0 = (i0 & 7) << 2;
            int r1 = i1 >> 3, c1 = (i1 & 7) << 2;
            float4 v0 = *(const float4*)(A + (m0 + r0) * DIN + kc + c0);
            float4 v1 = *(const float4*)(A + (m0 + r1) * DIN + kc + c1);
            As[r0 * 36 + c0 + 0] = v0.x; As[r0 * 36 + c0 + 1] = v0.y;
            As[r0 * 36 + c0 + 2] = v0.z; As[r0 * 36 + c0 + 3] = v0.w;
            As[r1 * 36 + c1 + 0] = v1.x; As[r1 * 36 + c1 + 1] = v1.y;
            As[r1 * 36 + c1 + 2] = v1.z; As[r1 * 36 + c1 + 3] = v1.w;
        }
        {
            int i0 = tid, i1 = tid + 256;
            int k0 = i0 >> 4, g0 = (i0 & 15) << 2;
            int k1 = i1 >> 4, g1 = (i1 & 15) << 2;
            *(float4*)(Bs + k0 * 64 + g0) =
                *(const float4*)(W + (kc + k0) * DOUT + n0 + g0);
            *(float4*)(Bs + k1 * 64 + g1) =
                *(const float4*)(W + (kc + k1) * DOUT + n0 + g1);
        }
        __syncthreads();

#pragma unroll
        for (int k = 0; k < 32; ++k) {
            float4 b4 = *(const float4*)(Bs + k * 64 + (tx << 2));
            float a0 = As[(ty * 4 + 0) * 36 + k];
            float a1 = As[(ty * 4 + 1) * 36 + k];
            float a2 = As[(ty * 4 + 2) * 36 + k];
            float a3 = As[(ty * 4 + 3) * 36 + k];
            acc[ 0] = __fmaf_rn(a0, b4.x, acc[ 0]);
            acc[ 1] = __fmaf_rn(a0, b4.y, acc[ 1]);
            acc[ 2] = __fmaf_rn(a0, b4.z, acc[ 2]);
            acc[ 3] = __fmaf_rn(a0, b4.w, acc[ 3]);
            acc[ 4] = __fmaf_rn(a1, b4.x, acc[ 4]);
            acc[ 5] = __fmaf_rn(a1, b4.y, acc[ 5]);
            acc[ 6] = __fmaf_rn(a1, b4.z, acc[ 6]);
            acc[ 7] = __fmaf_rn(a1, b4.w, acc[ 7]);
            acc[ 8] = __fmaf_rn(a2, b4.x, acc[ 8]);
            acc[ 9] = __fmaf_rn(a2, b4.y, acc[ 9]);
            acc[10] = __fmaf_rn(a2, b4.z, acc[10]);
            acc[11] = __fmaf_rn(a2, b4.w, acc[11]);
            acc[12] = __fmaf_rn(a3, b4.x, acc[12]);
            acc[13] = __fmaf_rn(a3, b4.y, acc[13]);
            acc[14] = __fmaf_rn(a3, b4.z, acc[14]);
            acc[15] = __fmaf_rn(a3, b4.w, acc[15]);
        }
    }

#pragma unroll
    for (int i = 0; i < 4; ++i) {
        float4 o;
        o.x = __fadd_rn(acc[i * 4 + 0], bias[(tx << 2) + 0]);
        o.y = __fadd_rn(acc[i * 4 + 1], bias[(tx << 2) + 1]);
        o.z = __fadd_rn(acc[i * 4 + 2], bias[(tx << 2) + 2]);
        o.w = __fadd_rn(acc[i * 4 + 3], bias[(tx << 2) + 3]);
        *(float4*)(C + (m0 + ty * 4 + i) * DOUT + n0 + (tx << 2)) = o;
    }
}

// ---------------------------------------------------------------------------
// Kernel 2: sequential scan, one CTA per batch row, thread j owns column j.
// Matvec is a STRICT single-accumulator ascending-k FMA chain (bit-exact to
// fp32 Eigen / cuBLAS accumulation), then + zx, then XLA tanh.
// W_h column j: rows 0..191 in registers, rows 192..255 in smem.
// ---------------------------------------------------------------------------
#define KREG 192
#define KSM  (DOUT - KREG)
#define SCAN_SMEM_BYTES ((KSM * DOUT + 2 * DOUT) * (int)sizeof(float))

__global__ __launch_bounds__(256, 1) void rnn_scan_kernel(
    const float* __restrict__ Wh,
    const float* __restrict__ h0,
    float* __restrict__ y,          // preloaded with zx, overwritten with y
    float* __restrict__ hfin)
{
    extern __shared__ float sm[];
    float* Ws   = sm;                 // [KSM][DOUT]
    float* hbuf = sm + KSM * DOUT;    // [2][DOUT]

    const int b = blockIdx.x;
    const int j = threadIdx.x;

    float w[KREG];
#pragma unroll
    for (int kk = 0; kk < KREG; ++kk)
        w[kk] = Wh[kk * DOUT + j];

    for (int idx = j; idx < KSM * DOUT; idx += 256)
        Ws[idx] = Wh[KREG * DOUT + idx];

    hbuf[j] = h0[b * DOUT + j];
    __syncthreads();

    float* yb = y + (size_t)b * SEQ * DOUT;
    int cur = 0;

    for (int t = 0; t < SEQ; ++t) {
        float zx = yb[(size_t)t * DOUT + j];   // prefetch early

        const float4* h4 = (const float4*)(hbuf + cur * DOUT);
        float acc = 0.f;

#pragma unroll
        for (int kk = 0; kk < KREG; kk += 4) {
            float4 hv = h4[kk >> 2];
            acc = __fmaf_rn(hv.x, w[kk + 0], acc);
            acc = __fmaf_rn(hv.y, w[kk + 1], acc);
            acc = __fmaf_rn(hv.z, w[kk + 2], acc);
            acc = __fmaf_rn(hv.w, w[kk + 3], acc);
        }
#pragma unroll
        for (int kk = 0; kk < KSM; kk += 4) {
            float4 hv = h4[(KREG + kk) >> 2];
            acc = __fmaf_rn(hv.x, Ws[(kk + 0) * DOUT + j], acc);
            acc = __fmaf_rn(hv.y, Ws[(kk + 1) * DOUT + j], acc);
            acc = __fmaf_rn(hv.z, Ws[(kk + 2) * DOUT + j], acc);
            acc = __fmaf_rn(hv.w, Ws[(kk + 3) * DOUT + j], acc);
        }

        float v = xla_tanh(__fadd_rn(acc, zx));
        yb[(size_t)t * DOUT + j] = v;
        hbuf[(cur ^ 1) * DOUT + j] = v;
        __syncthreads();
        cur ^= 1;
    }

    hfin[b * DOUT + j] = hbuf[cur * DOUT + j];
}

// ---------------------------------------------------------------------------
extern "C" void kernel_launch(void* const* d_in, const int* in_sizes, int n_in,
                              void* d_out, int out_size)
{
    const float* input = (const float*)d_in[0];
    const float* h0    = (const float*)d_in[1];
    const float* W_h   = (const float*)d_in[2];
    const float* W_x   = (const float*)d_in[3];
    const float* b_h   = (const float*)d_in[4];
    const float* b_x   = (const float*)d_in[5];

    float* y    = (float*)d_out;
    float* hfin = y + (size_t)BATCH * SEQ * DOUT;

    cudaFuncSetAttribute(rnn_scan_kernel,
                         cudaFuncAttributeMaxDynamicSharedMemorySize,
                         SCAN_SMEM_BYTES);

    dim3 g1(MTOT / 64, DOUT / 64);
    gemm_zx_kernel<<<g1, 256>>>(input, W_x, b_h, b_x, y);

    rnn_scan_kernel<<<BATCH, 256, SCAN_SMEM_BYTES>>>(W_h, h0, y, hfin);
}

// round 3
// speedup vs baseline: 1.0896x; 1.0896x over previous
#include <cuda_runtime.h>
#include <math.h>

#define BATCH 64
#define SEQ   2048
#define DIN   256
#define DOUT  256
#define MTOT  (BATCH * SEQ)

#define NSCAN   64                 // scan CTAs (one per batch row)
#define NWORK   84                 // GEMM producer CTAs
#define NCTA    (NSCAN + NWORK)    // 148 = one per SM, all wave-1 resident
#define CHUNK   64                 // timesteps per ready-flag chunk
#define NCHUNK  (SEQ / CHUNK)      // 32
#define NTILES  (NCHUNK * BATCH * 4)   // 8192 gemm tiles (64x64 each)

#define KREG 208
#define KSM  (DOUT - KREG)         // 48
#define SCAN_SMEM_BYTES ((KSM * DOUT + 2 * DOUT) * (int)sizeof(float))  // 51200

// per-(batch,chunk) readiness counters: 4 n-tiles must complete
__device__ int g_flags[BATCH * NCHUNK];

__global__ void reset_flags_kernel()
{
    int i = blockIdx.x * blockDim.x + threadIdx.x;
    if (i < BATCH * NCHUNK) g_flags[i] = 0;
}

// ---------------------------------------------------------------------------
// Bit-exact replica of XLA's EmitFastTanh (Eigen fast tanh, FMA variant).
// ---------------------------------------------------------------------------
__device__ __forceinline__ float xla_tanh(float x)
{
    const float kClamp = 7.99881172180175781f;
    const float kTiny  = 0.0004f;
    const float a1  = 4.89352455891786e-03f;
    const float a3  = 6.37261928875436e-04f;
    const float a5  = 1.48572235717979e-05f;
    const float a7  = 5.12229709037114e-08f;
    const float a9  = -8.60467152213735e-11f;
    const float a11 = 2.00018790482477e-13f;
    const float a13 = -2.76076847742355e-16f;
    const float b0  = 4.89352518554385e-03f;
    const float b2  = 2.26843463243900e-03f;
    const float b4  = 1.18534705686654e-04f;
    const float b6  = 1.19825839466702e-06f;

    float ax = fabsf(x);
    float xc = fminf(fmaxf(x, -kClamp), kClamp);
    float x2 = __fmul_rn(xc, xc);

    float p = __fmaf_rn(x2, a13, a11);
    p = __fmaf_rn(x2, p, a9);
    p = __fmaf_rn(x2, p, a7);
    p = __fmaf_rn(x2, p, a5);
    p = __fmaf_rn(x2, p, a3);
    p = __fmaf_rn(x2, p, a1);
    p = __fmul_rn(xc, p);

    float q = __fmaf_rn(x2, b6, b4);
    q = __fmaf_rn(x2, q, b2);
    q = __fmaf_rn(x2, q, b0);

    float r = __fdiv_rn(p, q);
    return (ax < kTiny) ? x : r;
}

// ---------------------------------------------------------------------------
// GEMM producer branch: computes zx = input @ W_x + (b_x+b_h) in 64x64 tiles,
// ordered by time-chunk so the scan consumers can stream behind it.
// Bit-exact: single fp32 accumulator per element, ascending k, fused FMA.
// ---------------------------------------------------------------------------
__device__ void gemm_worker(
    float* sm,
    int worker,
    const float* __restrict__ A,    // [MTOT][DIN]
    const float* __restrict__ W,    // [DIN][DOUT]
    const float* __restrict__ b_h,
    const float* __restrict__ b_x,
    float* __restrict__ C)          // [MTOT][DOUT]
{
    float* As   = sm;               // [64][36]
    float* Bs   = sm + 64 * 36;     // [32][64]
    float* bias = sm + 64 * 36 + 32 * 64;

    const int tid = threadIdx.x;
    const int tx = tid & 15;
    const int ty = tid >> 4;

    for (int tau = worker; tau < NTILES; tau += NWORK) {
        const int c  = tau >> 8;           // chunk 0..31 (ascending across loop)
        const int r  = tau & 255;
        const int bb = r >> 2;             // batch 0..63
        const int nq = r & 3;              // n-quarter
        const long m0 = (long)bb * SEQ + (long)c * CHUNK;
        const int n0 = nq * 64;

        if (tid < 64) bias[tid] = __fadd_rn(b_h[n0 + tid], b_x[n0 + tid]);

        float acc[16];
#pragma unroll
        for (int i = 0; i < 16; ++i) acc[i] = 0.f;

        for (int kc = 0; kc < DIN; kc += 32) {
            __syncthreads();
            {
                int i0 = tid, i1 = tid + 256;
                int r0 = i0 >> 3, c0 = (i0 & 7) << 2;
                int r1 = i1 >> 3, c1 = (i1 & 7) << 2;
                float4 v0 = *(const float4*)(A + (m0 + r0) * DIN + kc + c0);
                float4 v1 = *(const float4*)(A + (m0 + r1) * DIN + kc + c1);
                As[r0 * 36 + c0 + 0] = v0.x; As[r0 * 36 + c0 + 1] = v0.y;
                As[r0 * 36 + c0 + 2] = v0.z; As[r0 * 36 + c0 + 3] = v0.w;
                As[r1 * 36 + c1 + 0] = v1.x; As[r1 * 36 + c1 + 1] = v1.y;
                As[r1 * 36 + c1 + 2] = v1.z; As[r1 * 36 + c1 + 3] = v1.w;
            }
            {
                int i0 = tid, i1 = tid + 256;
                int k0 = i0 >> 4, g0 = (i0 & 15) << 2;
                int k1 = i1 >> 4, g1 = (i1 & 15) << 2;
                *(float4*)(Bs + k0 * 64 + g0) =
                    *(const float4*)(W + (kc + k0) * DOUT + n0 + g0);
                *(float4*)(Bs + k1 * 64 + g1) =
                    *(const float4*)(W + (kc + k1) * DOUT + n0 + g1);
            }
            __syncthreads();

#pragma unroll
            for (int k = 0; k < 32; ++k) {
                float4 b4 = *(const float4*)(Bs + k * 64 + (tx << 2));
                float a0 = As[(ty * 4 + 0) * 36 + k];
                float a1 = As[(ty * 4 + 1) * 36 + k];
                float a2 = As[(ty * 4 + 2) * 36 + k];
                float a3 = As[(ty * 4 + 3) * 36 + k];
                acc[ 0] = __fmaf_rn(a0, b4.x, acc[ 0]);
                acc[ 1] = __fmaf_rn(a0, b4.y, acc[ 1]);
                acc[ 2] = __fmaf_rn(a0, b4.z, acc[ 2]);
                acc[ 3] = __fmaf_rn(a0, b4.w, acc[ 3]);
                acc[ 4] = __fmaf_rn(a1, b4.x, acc[ 4]);
                acc[ 5] = __fmaf_rn(a1, b4.y, acc[ 5]);
                acc[ 6] = __fmaf_rn(a1, b4.z, acc[ 6]);
                acc[ 7] = __fmaf_rn(a1, b4.w, acc[ 7]);
                acc[ 8] = __fmaf_rn(a2, b4.x, acc[ 8]);
                acc[ 9] = __fmaf_rn(a2, b4.y, acc[ 9]);
                acc[10] = __fmaf_rn(a2, b4.z, acc[10]);
                acc[11] = __fmaf_rn(a2, b4.w, acc[11]);
                acc[12] = __fmaf_rn(a3, b4.x, acc[12]);
                acc[13] = __fmaf_rn(a3, b4.y, acc[13]);
                acc[14] = __fmaf_rn(a3, b4.z, acc[14]);
                acc[15] = __fmaf_rn(a3, b4.w, acc[15]);
            }
        }

#pragma unroll
        for (int i = 0; i < 4; ++i) {
            float4 o;
            o.x = __fadd_rn(acc[i * 4 + 0], bias[(tx << 2) + 0]);
            o.y = __fadd_rn(acc[i * 4 + 1], bias[(tx << 2) + 1]);
            o.z = __fadd_rn(acc[i * 4 + 2], bias[(tx << 2) + 2]);
            o.w = __fadd_rn(acc[i * 4 + 3], bias[(tx << 2) + 3]);
            *(float4*)(C + (m0 + ty * 4 + i) * DOUT + n0 + (tx << 2)) = o;
        }

        // Publish: stores -> fence -> CTA sync -> flag increment.
        __threadfence();
        __syncthreads();
        if (tid == 0) atomicAdd(&g_flags[bb * NCHUNK + c], 1);
    }
}

// ---------------------------------------------------------------------------
// Fused kernel: CTAs [0,64) run the sequential scan (one batch row each,
// thread j owns column j); CTAs [64,148) produce zx tiles. 148 CTAs = 1/SM,
// everything wave-1 resident -> producer/consumer spin is deadlock-free.
// ---------------------------------------------------------------------------
__global__ __launch_bounds__(256, 1) void rnn_fused_kernel(
    const float* __restrict__ input,
    const float* __restrict__ h0,
    const float* __restrict__ Wh,
    const float* __restrict__ Wx,
    const float* __restrict__ b_h,
    const float* __restrict__ b_x,
    float* __restrict__ y,          // zx written by producers, overwritten w/ y
    float* __restrict__ hfin)
{
    extern __shared__ float sm[];

    if (blockIdx.x >= NSCAN) {
        gemm_worker(sm, blockIdx.x - NSCAN, input, Wx, b_h, b_x, y);
        return;
    }

    // ---------------- scan branch ----------------
    float* Ws   = sm;                 // [KSM][DOUT]
    float* hbuf = sm + KSM * DOUT;    // [2][DOUT]

    const int b = blockIdx.x;
    const int j = threadIdx.x;

    float w[KREG];
#pragma unroll
    for (int kk = 0; kk < KREG; ++kk)
        w[kk] = Wh[kk * DOUT + j];

    for (int idx = j; idx < KSM * DOUT; idx += 256)
        Ws[idx] = Wh[KREG * DOUT + idx];

    hbuf[j] = h0[b * DOUT + j];
    __syncthreads();

    float* yb = y + (size_t)b * SEQ * DOUT;
    int cur = 0;

    for (int t = 0; t < SEQ; ++t) {
        if ((t & (CHUNK - 1)) == 0) {
            const int c = t / CHUNK;
            if (j == 0) {
                while (*(volatile int*)&g_flags[b * NCHUNK + c] != 4) { }
            }
            __syncthreads();
            __threadfence();          // acquire: order flag-read before zx loads
        }

        float zx = yb[(size_t)t * DOUT + j];   // hidden under the FMA chain

        const float4* h4 = (const float4*)(hbuf + cur * DOUT);
        float acc = 0.f;

#pragma unroll
        for (int kk = 0; kk < KREG; kk += 4) {
            float4 hv = h4[kk >> 2];
            acc = __fmaf_rn(hv.x, w[kk + 0], acc);
            acc = __fmaf_rn(hv.y, w[kk + 1], acc);
            acc = __fmaf_rn(hv.z, w[kk + 2], acc);
            acc = __fmaf_rn(hv.w, w[kk + 3], acc);
        }
#pragma unroll
        for (int kk = 0; kk < KSM; kk += 4) {
            float4 hv = h4[(KREG + kk) >> 2];
            acc = __fmaf_rn(hv.x, Ws[(kk + 0) * DOUT + j], acc);
            acc = __fmaf_rn(hv.y, Ws[(kk + 1) * DOUT + j], acc);
            acc = __fmaf_rn(hv.z, Ws[(kk + 2) * DOUT + j], acc);
            acc = __fmaf_rn(hv.w, Ws[(kk + 3) * DOUT + j], acc);
        }

        float v = xla_tanh(__fadd_rn(acc, zx));
        hbuf[(cur ^ 1) * DOUT + j] = v;
        __syncthreads();
        yb[(size_t)t * DOUT + j] = v;   // off the critical path
        cur ^= 1;
    }

    hfin[b * DOUT + j] = hbuf[cur * DOUT + j];
}

// ---------------------------------------------------------------------------
extern "C" void kernel_launch(void* const* d_in, const int* in_sizes, int n_in,
                              void* d_out, int out_size)
{
    const float* input = (const float*)d_in[0];
    const float* h0    = (const float*)d_in[1];
    const float* W_h   = (const float*)d_in[2];
    const float* W_x   = (const float*)d_in[3];
    const float* b_h   = (const float*)d_in[4];
    const float* b_x   = (const float*)d_in[5];

    float* y    = (float*)d_out;
    float* hfin = y + (size_t)BATCH * SEQ * DOUT;

    cudaFuncSetAttribute(rnn_fused_kernel,
                         cudaFuncAttributeMaxDynamicSharedMemorySize,
                         SCAN_SMEM_BYTES);

    reset_flags_kernel<<<8, 256>>>();
    rnn_fused_kernel<<<NCTA, 256, SCAN_SMEM_BYTES>>>(
        input, h0, W_h, W_x, b_h, b_x, y, hfin);
}